// round 2
// baseline (speedup 1.0000x reference)
#include <cuda_runtime.h>
#include <cuda_bf16.h>
#include <math.h>

// Problem constants
#define NN 4096
#define FF 1433
#define HH 32
#define CC 7
#define EE 131072

// ---------------- device scratch (no allocs allowed) ----------------
__device__ float g_A0[(size_t)NN * NN];      // level-0 adjacency (kept)
__device__ float g_Aaug[(size_t)NN * NN];    // augment scratch
__device__ float g_A1[(size_t)2048 * 2048];
__device__ float g_A2[(size_t)1024 * 1024];
__device__ float g_A3[(size_t)512 * 512];
__device__ float g_x0[NN * HH];
__device__ float g_xs0[NN * HH];
__device__ float g_xs1[2048 * HH];
__device__ float g_xs2[1024 * HH];
__device__ float g_hA[NN * HH];
__device__ float g_hB[NN * HH];
__device__ float g_Y[NN * HH];
__device__ float g_Yd[NN * HH];
__device__ float g_dinv[NN];
__device__ float g_score[NN];
__device__ int   g_perm[NN];                 // [0:2048) p0, [2048:3072) p1, [3072:3584) p2

// ---------------- kernels ----------------

__global__ void scatter_edges_k(const int* __restrict__ ei, float* __restrict__ A) {
    int e = blockIdx.x * blockDim.x + threadIdx.x;
    if (e < EE) {
        int u = ei[e], v = ei[EE + e];
        if (u != v) {
            A[(size_t)u * NN + v] = 1.0f;
            A[(size_t)v * NN + u] = 1.0f;
        }
    }
}

__global__ void rowsum_dinv_k(const float* __restrict__ A, float* __restrict__ dinv, int n) {
    __shared__ float sm[256];
    int row = blockIdx.x;
    float s = 0.f;
    const float* rp = A + (size_t)row * n;
    for (int j = threadIdx.x; j < n; j += 256) s += rp[j];
    sm[threadIdx.x] = s;
    __syncthreads();
    for (int o = 128; o > 0; o >>= 1) {
        if (threadIdx.x < o) sm[threadIdx.x] += sm[threadIdx.x + o];
        __syncthreads();
    }
    if (threadIdx.x == 0) dinv[row] = rsqrtf(sm[0] + 2.0f);
}

__global__ void scale_k(const float* __restrict__ Y, const float* __restrict__ dinv,
                        float* __restrict__ Yd, int n, int Nc) {
    int t = blockIdx.x * blockDim.x + threadIdx.x;
    if (t < n * Nc) Yd[t] = Y[t] * dinv[t / Nc];
}

// Generic tiled SGEMM: C[M,N] = A[M,K] @ B[K,N]  (row-major, lda=K, ldb=ldc=N)
// mode 0: plain        mode 1: augment (C = A@A + 2A, zero diag; B==A, M==N==K)
// mode 2: gcn epilogue (C = dinv[r]*(acc + 2*B[r,c]) + bias[c]; B is Yd with K==M)
__global__ void sgemm_k(const float* __restrict__ A, const float* __restrict__ B,
                        float* __restrict__ C, int M, int N, int K,
                        int mode, const float* __restrict__ dinv,
                        const float* __restrict__ bias, int relu) {
    __shared__ __align__(16) float As[16][68];
    __shared__ __align__(16) float Bs[16][68];
    int tx = threadIdx.x, ty = threadIdx.y;
    int t = ty * 16 + tx;
    int m0 = blockIdx.y * 64, n0 = blockIdx.x * 64;
    float acc[4][4] = {};

    for (int k0 = 0; k0 < K; k0 += 16) {
#pragma unroll
        for (int q = 0; q < 4; q++) {
            int idx = t + q * 256;
            int m = idx >> 4, k = idx & 15;
            int gm = m0 + m, gk = k0 + k;
            As[k][m] = (gm < M && gk < K) ? A[(size_t)gm * K + gk] : 0.f;
        }
#pragma unroll
        for (int q = 0; q < 4; q++) {
            int idx = t + q * 256;
            int k = idx >> 6, n = idx & 63;
            int gk = k0 + k, gn = n0 + n;
            Bs[k][n] = (gk < K && gn < N) ? B[(size_t)gk * N + gn] : 0.f;
        }
        __syncthreads();
#pragma unroll
        for (int kk = 0; kk < 16; kk++) {
            float4 a4 = *(const float4*)&As[kk][ty * 4];
            float4 b4 = *(const float4*)&Bs[kk][tx * 4];
            float a[4] = {a4.x, a4.y, a4.z, a4.w};
            float b[4] = {b4.x, b4.y, b4.z, b4.w};
#pragma unroll
            for (int i = 0; i < 4; i++)
#pragma unroll
                for (int j = 0; j < 4; j++) acc[i][j] += a[i] * b[j];
        }
        __syncthreads();
    }

#pragma unroll
    for (int i = 0; i < 4; i++) {
        int r = m0 + ty * 4 + i;
        if (r >= M) continue;
#pragma unroll
        for (int j = 0; j < 4; j++) {
            int c = n0 + tx * 4 + j;
            if (c >= N) continue;
            float v = acc[i][j];
            if (mode == 1) {
                v += 2.0f * A[(size_t)r * K + c];
                if (r == c) v = 0.0f;
            } else if (mode == 2) {
                v = dinv[r] * (v + 2.0f * B[(size_t)r * N + c]) + bias[c];
            }
            if (relu) v = fmaxf(v, 0.0f);
            C[(size_t)r * N + c] = v;
        }
    }
}

__global__ void score_k(const float* __restrict__ h, const float* __restrict__ p,
                        float* __restrict__ score, int n) {
    __shared__ float ps[HH];
    __shared__ float pn;
    if (threadIdx.x < HH) ps[threadIdx.x] = p[threadIdx.x];
    __syncthreads();
    if (threadIdx.x == 0) {
        float s = 0.f;
        for (int i = 0; i < HH; i++) s += ps[i] * ps[i];
        pn = sqrtf(s);
    }
    __syncthreads();
    int i = blockIdx.x * blockDim.x + threadIdx.x;
    if (i < n) {
        float s = 0.f;
        const float* hp = h + (size_t)i * HH;
#pragma unroll
        for (int c = 0; c < HH; c++) s += hp[c] * ps[c];
        score[i] = tanhf(s / pn);
    }
}

// single-block bitonic sort; key = (descending score, ascending index)
__global__ void sort_topk_k(const float* __restrict__ score, int n,
                            int* __restrict__ perm, int k) {
    __shared__ unsigned long long sk[4096];
    int tid = threadIdx.x;
    for (int i = tid; i < n; i += 1024) {
        unsigned u = __float_as_uint(score[i]);
        u = (u & 0x80000000u) ? ~u : (u | 0x80000000u);
        sk[i] = ((unsigned long long)(~u) << 32) | (unsigned)i;
    }
    __syncthreads();
    for (int kk = 2; kk <= n; kk <<= 1) {
        for (int j = kk >> 1; j > 0; j >>= 1) {
            for (int idx = tid; idx < n; idx += 1024) {
                int ixj = idx ^ j;
                if (ixj > idx) {
                    bool up = ((idx & kk) == 0);
                    unsigned long long a = sk[idx], b = sk[ixj];
                    if ((a > b) == up) { sk[idx] = b; sk[ixj] = a; }
                }
            }
            __syncthreads();
        }
    }
    for (int r = tid; r < k; r += 1024) perm[r] = (int)(sk[r] & 0xffffffffULL);
}

__global__ void gather_h_k(const float* __restrict__ h, const int* __restrict__ perm,
                           const float* __restrict__ score, float* __restrict__ out, int k) {
    int t = blockIdx.x * blockDim.x + threadIdx.x;
    if (t < k * HH) {
        int r = t >> 5, c = t & 31;
        int p = perm[r];
        out[t] = h[(size_t)p * HH + c] * score[p];
    }
}

__global__ void gather_A_k(const float* __restrict__ Aaug, int n,
                           const int* __restrict__ perm, float* __restrict__ outA, int k) {
    long total = (long)k * k;
    for (long t = blockIdx.x * (long)blockDim.x + threadIdx.x; t < total;
         t += (long)gridDim.x * blockDim.x) {
        int r = (int)(t / k), s = (int)(t % k);
        outA[t] = Aaug[(size_t)perm[r] * n + perm[s]];
    }
}

__global__ void scatter_add_k(float* __restrict__ dst, const float* __restrict__ src,
                              const int* __restrict__ perm, int k) {
    int t = blockIdx.x * blockDim.x + threadIdx.x;
    if (t < k * HH) {
        int r = t >> 5, c = t & 31;
        dst[(size_t)perm[r] * HH + c] += src[t];
    }
}

__global__ void logsoftmax_k(const float* __restrict__ X, float* __restrict__ out, int n) {
    int r = blockIdx.x * blockDim.x + threadIdx.x;
    if (r < n) {
        const float* xp = X + (size_t)r * CC;
        float m = -1e30f;
#pragma unroll
        for (int j = 0; j < CC; j++) m = fmaxf(m, xp[j]);
        float s = 0.f;
#pragma unroll
        for (int j = 0; j < CC; j++) s += expf(xp[j] - m);
        float l = logf(s);
        float* op = out + (size_t)r * CC;
#pragma unroll
        for (int j = 0; j < CC; j++) op[j] = xp[j] - m - l;
    }
}

// ---------------- host side ----------------

static inline dim3 sgemm_grid(int M, int N) { return dim3((N + 63) / 64, (M + 63) / 64); }

static void run_gcn(const float* X, const float* A, int n, int Kin, int Nout,
                    const float* W, const float* b, int relu, float* out,
                    float* pY, float* pYd, float* pdinv) {
    rowsum_dinv_k<<<n, 256>>>(A, pdinv, n);
    sgemm_k<<<sgemm_grid(n, Nout), dim3(16, 16)>>>(X, W, pY, n, Nout, Kin, 0, nullptr, nullptr, 0);
    int tot = n * Nout;
    scale_k<<<(tot + 255) / 256, 256>>>(pY, pdinv, pYd, n, Nout);
    sgemm_k<<<sgemm_grid(n, Nout), dim3(16, 16)>>>(A, pYd, out, n, Nout, n, 2, pdinv, b, relu);
}

extern "C" void kernel_launch(void* const* d_in, const int* in_sizes, int n_in,
                              void* d_out, int out_size) {
    const float* x   = (const float*)d_in[0];
    const int*   ei  = (const int*)d_in[1];
    const float* Wi  = (const float*)d_in[2];
    const float* bi  = (const float*)d_in[3];
    const float* dW  = (const float*)d_in[4];   // (4,32,32)
    const float* db  = (const float*)d_in[5];   // (4,32)
    const float* pp  = (const float*)d_in[6];   // (3,32)
    const float* uW  = (const float*)d_in[7];   // (3,32,32)
    const float* ub  = (const float*)d_in[8];   // (3,32)
    const float* Wf  = (const float*)d_in[9];   // (32,7)
    const float* bf  = (const float*)d_in[10];  // (7)
    float* out = (float*)d_out;

    float *pA0, *pAaug, *pA1, *pA2, *pA3;
    float *px0, *pxs0, *pxs1, *pxs2, *phA, *phB, *pY, *pYd, *pdinv, *pscore;
    int* pperm;
    cudaGetSymbolAddress((void**)&pA0, g_A0);
    cudaGetSymbolAddress((void**)&pAaug, g_Aaug);
    cudaGetSymbolAddress((void**)&pA1, g_A1);
    cudaGetSymbolAddress((void**)&pA2, g_A2);
    cudaGetSymbolAddress((void**)&pA3, g_A3);
    cudaGetSymbolAddress((void**)&px0, g_x0);
    cudaGetSymbolAddress((void**)&pxs0, g_xs0);
    cudaGetSymbolAddress((void**)&pxs1, g_xs1);
    cudaGetSymbolAddress((void**)&pxs2, g_xs2);
    cudaGetSymbolAddress((void**)&phA, g_hA);
    cudaGetSymbolAddress((void**)&phB, g_hB);
    cudaGetSymbolAddress((void**)&pY, g_Y);
    cudaGetSymbolAddress((void**)&pYd, g_Yd);
    cudaGetSymbolAddress((void**)&pdinv, g_dinv);
    cudaGetSymbolAddress((void**)&pscore, g_score);
    cudaGetSymbolAddress((void**)&pperm, g_perm);

    int* pp0 = pperm;
    int* pp1 = pperm + 2048;
    int* pp2 = pperm + 3072;

    // ---- build adjacency ----
    cudaMemsetAsync(pA0, 0, (size_t)NN * NN * sizeof(float));
    scatter_edges_k<<<(EE + 255) / 256, 256>>>(ei, pA0);

    // ---- x = relu(gcn(x, A, Wi, bi)) ----
    run_gcn(x, pA0, NN, FF, HH, Wi, bi, 1, px0, pY, pYd, pdinv);
    // ---- h = relu(gcn(x, A, dW0, db0)) -> xs[0] ----
    run_gcn(px0, pA0, NN, HH, HH, dW, db, 1, pxs0, pY, pYd, pdinv);

    // ================= down path =================
    // i = 1 (4096 -> 2048)
    sgemm_k<<<sgemm_grid(NN, NN), dim3(16, 16)>>>(pA0, pA0, pAaug, NN, NN, NN, 1, nullptr, nullptr, 0);
    score_k<<<(NN + 255) / 256, 256>>>(pxs0, pp + 0, pscore, NN);
    sort_topk_k<<<1, 1024>>>(pscore, NN, pp0, 2048);
    gather_h_k<<<(2048 * HH + 255) / 256, 256>>>(pxs0, pp0, pscore, phA, 2048);
    gather_A_k<<<4096, 256>>>(pAaug, NN, pp0, pA1, 2048);
    run_gcn(phA, pA1, 2048, HH, HH, dW + 1024, db + 32, 1, pxs1, pY, pYd, pdinv);

    // i = 2 (2048 -> 1024)
    sgemm_k<<<sgemm_grid(2048, 2048), dim3(16, 16)>>>(pA1, pA1, pAaug, 2048, 2048, 2048, 1, nullptr, nullptr, 0);
    score_k<<<(2048 + 255) / 256, 256>>>(pxs1, pp + 32, pscore, 2048);
    sort_topk_k<<<1, 1024>>>(pscore, 2048, pp1, 1024);
    gather_h_k<<<(1024 * HH + 255) / 256, 256>>>(pxs1, pp1, pscore, phA, 1024);
    gather_A_k<<<2048, 256>>>(pAaug, 2048, pp1, pA2, 1024);
    run_gcn(phA, pA2, 1024, HH, HH, dW + 2048, db + 64, 1, pxs2, pY, pYd, pdinv);

    // i = 3 (1024 -> 512)
    sgemm_k<<<sgemm_grid(1024, 1024), dim3(16, 16)>>>(pA2, pA2, pAaug, 1024, 1024, 1024, 1, nullptr, nullptr, 0);
    score_k<<<(1024 + 255) / 256, 256>>>(pxs2, pp + 64, pscore, 1024);
    sort_topk_k<<<1, 1024>>>(pscore, 1024, pp2, 512);
    gather_h_k<<<(512 * HH + 255) / 256, 256>>>(pxs2, pp2, pscore, phA, 512);
    gather_A_k<<<1024, 256>>>(pAaug, 1024, pp2, pA3, 512);
    run_gcn(phA, pA3, 512, HH, HH, dW + 3072, db + 96, 1, phB, pY, pYd, pdinv);

    // ================= up path =================
    // i = 0, j = 2 (512 -> 1024)
    cudaMemcpyAsync(phA, pxs2, (size_t)1024 * HH * sizeof(float), cudaMemcpyDeviceToDevice);
    scatter_add_k<<<(512 * HH + 255) / 256, 256>>>(phA, phB, pp2, 512);
    run_gcn(phA, pA2, 1024, HH, HH, uW, ub, 1, phB, pY, pYd, pdinv);

    // i = 1, j = 1 (1024 -> 2048)
    cudaMemcpyAsync(phA, pxs1, (size_t)2048 * HH * sizeof(float), cudaMemcpyDeviceToDevice);
    scatter_add_k<<<(1024 * HH + 255) / 256, 256>>>(phA, phB, pp1, 1024);
    run_gcn(phA, pA1, 2048, HH, HH, uW + 1024, ub + 32, 1, phB, pY, pYd, pdinv);

    // i = 2, j = 0 (2048 -> 4096); no relu in loop, but x = relu(h) right after,
    // so relu here is equivalent.
    cudaMemcpyAsync(phA, pxs0, (size_t)NN * HH * sizeof(float), cudaMemcpyDeviceToDevice);
    scatter_add_k<<<(2048 * HH + 255) / 256, 256>>>(phA, phB, pp0, 2048);
    run_gcn(phA, pA0, NN, HH, HH, uW + 2048, ub + 64, 1, phB, pY, pYd, pdinv);

    // ---- final gcn + log_softmax ----
    run_gcn(phB, pA0, NN, HH, CC, Wf, bf, 0, phA, pY, pYd, pdinv);
    logsoftmax_k<<<(NN + 255) / 256, 256>>>(phA, out, NN);
}

// round 4
// speedup vs baseline: 3.1385x; 3.1385x over previous
#include <cuda_runtime.h>
#include <cuda_bf16.h>
#include <math.h>
#include <stdint.h>

// Problem constants
#define NN 4096
#define FF 1433
#define HH 32
#define CC 7
#define EE 131072

// ---------------- device scratch (no allocs allowed) ----------------
__device__ float g_A0[(size_t)NN * NN];
__device__ float g_Aaug[(size_t)NN * NN];
__device__ float g_A1[(size_t)2048 * 2048];
__device__ float g_A2[(size_t)1024 * 1024];
__device__ float g_A3[(size_t)512 * 512];
__device__ float g_x0[NN * HH];
__device__ float g_xs0[NN * HH];
__device__ float g_xs1[2048 * HH];
__device__ float g_xs2[1024 * HH];
__device__ float g_hA[NN * HH];
__device__ float g_hB[NN * HH];
__device__ float g_Y[NN * HH];
__device__ float g_Yd[NN * HH];
__device__ float g_dinv[NN];
__device__ float g_score[NN];
__device__ int   g_perm[NN];

// ---------------- tensor-core augment via mma.sync tf32 ----------------
// C = A@A + 2A, zero diag; A symmetric, n multiple of 128.
// 128x128 CTA tile, lower triangle only, mirrored via smem transpose.
// 8 warps: 2 (m) x 4 (n); warp tile 64x32 = 4x4 m16n8 fragments, k-chunks of 32.
#define ASTRIDE 36
#define CSTRIDE 129

__global__ void __launch_bounds__(256, 2) augment_mma_k(const float* __restrict__ A,
                                                        float* __restrict__ C, int n) {
    extern __shared__ float sm[];
    float* sA = sm;                 // [128][ASTRIDE]
    float* sB = sm + 128 * ASTRIDE; // [128][ASTRIDE]

    int tid = threadIdx.x;
    int wid = tid >> 5, lane = tid & 31;
    int wm = wid >> 2, wn = wid & 3;
    int lr = lane >> 2, lc = lane & 3;

    // tile id -> (bx, by) lower triangle (by >= bx)
    int t = blockIdx.x;
    int by = (int)((sqrtf(8.0f * (float)t + 1.0f) - 1.0f) * 0.5f);
    while ((by + 1) * (by + 2) / 2 <= t) by++;
    while (by * (by + 1) / 2 > t) by--;
    int bx = t - by * (by + 1) / 2;
    int m0 = by * 128, n0 = bx * 128;

    float acc[4][4][4];
#pragma unroll
    for (int i = 0; i < 4; i++)
#pragma unroll
        for (int j = 0; j < 4; j++)
#pragma unroll
            for (int q = 0; q < 4; q++) acc[i][j][q] = 0.f;

    int nch = n >> 5;
    for (int ch = 0; ch < nch; ch++) {
        int k0 = ch << 5;
        // load 128x32 A-tile (rows m0..) and B-tile (rows n0..) into smem
#pragma unroll
        for (int q = 0; q < 4; q++) {
            int idx = tid + q * 256;         // 0..1023 float4 slots
            int row = idx >> 3, c4 = idx & 7;
            float4 va = *(const float4*)&A[(size_t)(m0 + row) * n + k0 + c4 * 4];
            *(float4*)&sA[row * ASTRIDE + c4 * 4] = va;
            float4 vb = *(const float4*)&A[(size_t)(n0 + row) * n + k0 + c4 * 4];
            *(float4*)&sB[row * ASTRIDE + c4 * 4] = vb;
        }
        __syncthreads();
#pragma unroll
        for (int kt = 0; kt < 4; kt++) {
            int kk = kt * 8;
            uint32_t a[4][4];
#pragma unroll
            for (int i = 0; i < 4; i++) {
                int r0 = wm * 64 + i * 16;
                a[i][0] = __float_as_uint(sA[(r0 + lr) * ASTRIDE + kk + lc]);
                a[i][1] = __float_as_uint(sA[(r0 + lr + 8) * ASTRIDE + kk + lc]);
                a[i][2] = __float_as_uint(sA[(r0 + lr) * ASTRIDE + kk + lc + 4]);
                a[i][3] = __float_as_uint(sA[(r0 + lr + 8) * ASTRIDE + kk + lc + 4]);
            }
#pragma unroll
            for (int j = 0; j < 4; j++) {
                int c0 = wn * 32 + j * 8;
                uint32_t b0 = __float_as_uint(sB[(c0 + lr) * ASTRIDE + kk + lc]);
                uint32_t b1 = __float_as_uint(sB[(c0 + lr) * ASTRIDE + kk + lc + 4]);
#pragma unroll
                for (int i = 0; i < 4; i++) {
                    asm volatile(
                        "mma.sync.aligned.m16n8k8.row.col.f32.tf32.tf32.f32 "
                        "{%0,%1,%2,%3}, {%4,%5,%6,%7}, {%8,%9}, {%0,%1,%2,%3};"
                        : "+f"(acc[i][j][0]), "+f"(acc[i][j][1]),
                          "+f"(acc[i][j][2]), "+f"(acc[i][j][3])
                        : "r"(a[i][0]), "r"(a[i][1]), "r"(a[i][2]), "r"(a[i][3]),
                          "r"(b0), "r"(b1));
                }
            }
        }
        __syncthreads();
    }

    // stage raw accumulators into smem tile sC[128][CSTRIDE]
    float* sC = sm;
#pragma unroll
    for (int i = 0; i < 4; i++) {
#pragma unroll
        for (int j = 0; j < 4; j++) {
            int r0 = wm * 64 + i * 16 + lr;
            int c0 = wn * 32 + j * 8 + 2 * lc;
            sC[r0 * CSTRIDE + c0]           = acc[i][j][0];
            sC[r0 * CSTRIDE + c0 + 1]       = acc[i][j][1];
            sC[(r0 + 8) * CSTRIDE + c0]     = acc[i][j][2];
            sC[(r0 + 8) * CSTRIDE + c0 + 1] = acc[i][j][3];
        }
    }
    __syncthreads();

    // coalesced epilogue writes (+2A, zero diag), plus mirror for off-diag tiles
    for (int e = tid; e < 128 * 128; e += 256) {
        int r = e >> 7, c = e & 127;
        float v = sC[r * CSTRIDE + c] + 2.0f * A[(size_t)(m0 + r) * n + n0 + c];
        if (m0 + r == n0 + c) v = 0.0f;
        C[(size_t)(m0 + r) * n + n0 + c] = v;
    }
    if (bx != by) {
        for (int e = tid; e < 128 * 128; e += 256) {
            int r = e >> 7, c = e & 127;
            float v = sC[c * CSTRIDE + r] + 2.0f * A[(size_t)(n0 + r) * n + m0 + c];
            C[(size_t)(n0 + r) * n + m0 + c] = v;
        }
    }
}

// ---------------- simple kernels ----------------

__global__ void scatter_edges_k(const int* __restrict__ ei, float* __restrict__ A) {
    int e = blockIdx.x * blockDim.x + threadIdx.x;
    if (e < EE) {
        int u = ei[e], v = ei[EE + e];
        if (u != v) {
            A[(size_t)u * NN + v] = 1.0f;
            A[(size_t)v * NN + u] = 1.0f;
        }
    }
}

__global__ void rowsum_dinv_k(const float* __restrict__ A, float* __restrict__ dinv, int n) {
    __shared__ float sm[256];
    int row = blockIdx.x;
    float s = 0.f;
    const float* rp = A + (size_t)row * n;
    for (int j = threadIdx.x; j < n; j += 256) s += rp[j];
    sm[threadIdx.x] = s;
    __syncthreads();
    for (int o = 128; o > 0; o >>= 1) {
        if (threadIdx.x < o) sm[threadIdx.x] += sm[threadIdx.x + o];
        __syncthreads();
    }
    if (threadIdx.x == 0) dinv[row] = rsqrtf(sm[0] + 2.0f);
}

__global__ void scale_k(const float* __restrict__ Y, const float* __restrict__ dinv,
                        float* __restrict__ Yd, int n, int Nc) {
    int t = blockIdx.x * blockDim.x + threadIdx.x;
    if (t < n * Nc) Yd[t] = Y[t] * dinv[t / Nc];
}

// fp32 SGEMM kept only for level-2 augment: C = A@A + 2A, zero diag
__global__ void sgemm_k(const float* __restrict__ A, const float* __restrict__ B,
                        float* __restrict__ C, int M, int N, int K) {
    __shared__ __align__(16) float As[16][68];
    __shared__ __align__(16) float Bs[16][68];
    int tx = threadIdx.x, ty = threadIdx.y;
    int t = ty * 16 + tx;
    int m0 = blockIdx.y * 64, n0 = blockIdx.x * 64;
    float acc[4][4] = {};

    for (int k0 = 0; k0 < K; k0 += 16) {
#pragma unroll
        for (int q = 0; q < 4; q++) {
            int idx = t + q * 256;
            int m = idx >> 4, k = idx & 15;
            As[k][m] = A[(size_t)(m0 + m) * K + k0 + k];
        }
#pragma unroll
        for (int q = 0; q < 4; q++) {
            int idx = t + q * 256;
            int k = idx >> 6, n = idx & 63;
            Bs[k][n] = B[(size_t)(k0 + k) * N + n0 + n];
        }
        __syncthreads();
#pragma unroll
        for (int kk = 0; kk < 16; kk++) {
            float4 a4 = *(const float4*)&As[kk][ty * 4];
            float4 b4 = *(const float4*)&Bs[kk][tx * 4];
            float a[4] = {a4.x, a4.y, a4.z, a4.w};
            float b[4] = {b4.x, b4.y, b4.z, b4.w};
#pragma unroll
            for (int i = 0; i < 4; i++)
#pragma unroll
                for (int j = 0; j < 4; j++) acc[i][j] += a[i] * b[j];
        }
        __syncthreads();
    }

#pragma unroll
    for (int i = 0; i < 4; i++) {
        int r = m0 + ty * 4 + i;
#pragma unroll
        for (int j = 0; j < 4; j++) {
            int c = n0 + tx * 4 + j;
            float v = acc[i][j] + 2.0f * A[(size_t)r * K + c];
            if (r == c) v = 0.0f;
            C[(size_t)r * N + c] = v;
        }
    }
}

// Narrow GEMM: C[M,N<=32] = A[M,K] @ B[K,N]
// mode 0: plain    mode 2: gcn epilogue C = dinv[r]*(acc + 2*B[r,c]) + bias[c]
__global__ void gemm_n32_k(const float* __restrict__ A, const float* __restrict__ B,
                           float* __restrict__ C, int M, int N, int K, int mode,
                           const float* __restrict__ dinv, const float* __restrict__ bias,
                           int relu) {
    __shared__ __align__(16) float As[32][33];
    __shared__ __align__(16) float Bs[32][32];
    int tid = threadIdx.x;
    int m0 = blockIdx.x * 32;
    int r = tid >> 3, cg = (tid & 7) * 4;
    float acc[4] = {};
    for (int k0 = 0; k0 < K; k0 += 32) {
#pragma unroll
        for (int q = 0; q < 4; q++) {
            int e = tid + q * 256;
            int row = e >> 5, col = e & 31;
            int gr = m0 + row, gk = k0 + col;
            As[row][col] = (gr < M && gk < K) ? A[(size_t)gr * K + gk] : 0.f;
            int bk = k0 + row;
            Bs[row][col] = (bk < K && col < N) ? B[(size_t)bk * N + col] : 0.f;
        }
        __syncthreads();
#pragma unroll
        for (int kk = 0; kk < 32; kk++) {
            float a = As[r][kk];
            float4 b = *(const float4*)&Bs[kk][cg];
            acc[0] += a * b.x; acc[1] += a * b.y; acc[2] += a * b.z; acc[3] += a * b.w;
        }
        __syncthreads();
    }
    int gr = m0 + r;
    if (gr < M) {
#pragma unroll
        for (int j = 0; j < 4; j++) {
            int c = cg + j;
            if (c < N) {
                float v = acc[j];
                if (mode == 2) v = dinv[gr] * (v + 2.0f * B[(size_t)gr * N + c]) + bias[c];
                if (relu) v = fmaxf(v, 0.0f);
                C[(size_t)gr * N + c] = v;
            }
        }
    }
}

__global__ void score_k(const float* __restrict__ h, const float* __restrict__ p,
                        float* __restrict__ score, int n) {
    __shared__ float ps[HH];
    __shared__ float pn;
    if (threadIdx.x < HH) ps[threadIdx.x] = p[threadIdx.x];
    __syncthreads();
    if (threadIdx.x == 0) {
        float s = 0.f;
        for (int i = 0; i < HH; i++) s += ps[i] * ps[i];
        pn = sqrtf(s);
    }
    __syncthreads();
    int i = blockIdx.x * blockDim.x + threadIdx.x;
    if (i < n) {
        float s = 0.f;
        const float* hp = h + (size_t)i * HH;
#pragma unroll
        for (int c = 0; c < HH; c++) s += hp[c] * ps[c];
        score[i] = tanhf(s / pn);
    }
}

__global__ void sort_topk_k(const float* __restrict__ score, int n,
                            int* __restrict__ perm, int k) {
    __shared__ unsigned long long sk[4096];
    int tid = threadIdx.x;
    for (int i = tid; i < n; i += 1024) {
        unsigned u = __float_as_uint(score[i]);
        u = (u & 0x80000000u) ? ~u : (u | 0x80000000u);
        sk[i] = ((unsigned long long)(~u) << 32) | (unsigned)i;
    }
    __syncthreads();
    for (int kk = 2; kk <= n; kk <<= 1) {
        for (int j = kk >> 1; j > 0; j >>= 1) {
            for (int idx = tid; idx < n; idx += 1024) {
                int ixj = idx ^ j;
                if (ixj > idx) {
                    bool up = ((idx & kk) == 0);
                    unsigned long long a = sk[idx], b = sk[ixj];
                    if ((a > b) == up) { sk[idx] = b; sk[ixj] = a; }
                }
            }
            __syncthreads();
        }
    }
    for (int r = tid; r < k; r += 1024) perm[r] = (int)(sk[r] & 0xffffffffULL);
}

__global__ void gather_h_k(const float* __restrict__ h, const int* __restrict__ perm,
                           const float* __restrict__ score, float* __restrict__ out, int k) {
    int t = blockIdx.x * blockDim.x + threadIdx.x;
    if (t < k * HH) {
        int r = t >> 5, c = t & 31;
        int p = perm[r];
        out[t] = h[(size_t)p * HH + c] * score[p];
    }
}

__global__ void gather_A_k(const float* __restrict__ Aaug, int n,
                           const int* __restrict__ perm, float* __restrict__ outA, int k) {
    long total = (long)k * k;
    for (long t = blockIdx.x * (long)blockDim.x + threadIdx.x; t < total;
         t += (long)gridDim.x * blockDim.x) {
        int r = (int)(t / k), s = (int)(t % k);
        outA[t] = Aaug[(size_t)perm[r] * n + perm[s]];
    }
}

__global__ void scatter_add_k(float* __restrict__ dst, const float* __restrict__ src,
                              const int* __restrict__ perm, int k) {
    int t = blockIdx.x * blockDim.x + threadIdx.x;
    if (t < k * HH) {
        int r = t >> 5, c = t & 31;
        dst[(size_t)perm[r] * HH + c] += src[t];
    }
}

__global__ void logsoftmax_k(const float* __restrict__ X, float* __restrict__ out, int n) {
    int r = blockIdx.x * blockDim.x + threadIdx.x;
    if (r < n) {
        const float* xp = X + (size_t)r * CC;
        float m = -1e30f;
#pragma unroll
        for (int j = 0; j < CC; j++) m = fmaxf(m, xp[j]);
        float s = 0.f;
#pragma unroll
        for (int j = 0; j < CC; j++) s += expf(xp[j] - m);
        float l = logf(s);
        float* op = out + (size_t)r * CC;
#pragma unroll
        for (int j = 0; j < CC; j++) op[j] = xp[j] - m - l;
    }
}

// ---------------- host side ----------------

static void run_gcn(const float* X, const float* A, int n, int Kin, int Nout,
                    const float* W, const float* b, int relu, float* out,
                    float* pY, float* pYd, float* pdinv) {
    rowsum_dinv_k<<<n, 256>>>(A, pdinv, n);
    gemm_n32_k<<<(n + 31) / 32, 256>>>(X, W, pY, n, Nout, Kin, 0, nullptr, nullptr, 0);
    int tot = n * Nout;
    scale_k<<<(tot + 255) / 256, 256>>>(pY, pdinv, pYd, n, Nout);
    gemm_n32_k<<<(n + 31) / 32, 256>>>(A, pYd, out, n, Nout, n, 2, pdinv, b, relu);
}

#define AUG_SMEM (128 * CSTRIDE * 4)   // 66048 bytes (> 2*128*ASTRIDE*4 = 36864)

extern "C" void kernel_launch(void* const* d_in, const int* in_sizes, int n_in,
                              void* d_out, int out_size) {
    const float* x   = (const float*)d_in[0];
    const int*   ei  = (const int*)d_in[1];
    const float* Wi  = (const float*)d_in[2];
    const float* bi  = (const float*)d_in[3];
    const float* dW  = (const float*)d_in[4];
    const float* db  = (const float*)d_in[5];
    const float* pp  = (const float*)d_in[6];
    const float* uW  = (const float*)d_in[7];
    const float* ub  = (const float*)d_in[8];
    const float* Wf  = (const float*)d_in[9];
    const float* bf  = (const float*)d_in[10];
    float* out = (float*)d_out;

    cudaFuncSetAttribute(augment_mma_k, cudaFuncAttributeMaxDynamicSharedMemorySize, AUG_SMEM);

    float *pA0, *pAaug, *pA1, *pA2, *pA3;
    float *px0, *pxs0, *pxs1, *pxs2, *phA, *phB, *pY, *pYd, *pdinv, *pscore;
    int* pperm;
    cudaGetSymbolAddress((void**)&pA0, g_A0);
    cudaGetSymbolAddress((void**)&pAaug, g_Aaug);
    cudaGetSymbolAddress((void**)&pA1, g_A1);
    cudaGetSymbolAddress((void**)&pA2, g_A2);
    cudaGetSymbolAddress((void**)&pA3, g_A3);
    cudaGetSymbolAddress((void**)&px0, g_x0);
    cudaGetSymbolAddress((void**)&pxs0, g_xs0);
    cudaGetSymbolAddress((void**)&pxs1, g_xs1);
    cudaGetSymbolAddress((void**)&pxs2, g_xs2);
    cudaGetSymbolAddress((void**)&phA, g_hA);
    cudaGetSymbolAddress((void**)&phB, g_hB);
    cudaGetSymbolAddress((void**)&pY, g_Y);
    cudaGetSymbolAddress((void**)&pYd, g_Yd);
    cudaGetSymbolAddress((void**)&pdinv, g_dinv);
    cudaGetSymbolAddress((void**)&pscore, g_score);
    cudaGetSymbolAddress((void**)&pperm, g_perm);

    int* pp0 = pperm;
    int* pp1 = pperm + 2048;
    int* pp2 = pperm + 3072;

    // ---- build adjacency ----
    cudaMemsetAsync(pA0, 0, (size_t)NN * NN * sizeof(float));
    scatter_edges_k<<<(EE + 255) / 256, 256>>>(ei, pA0);

    // ---- x = relu(gcn(x, A, Wi, bi)); h = relu(gcn(x, A, dW0, db0)) ----
    run_gcn(x, pA0, NN, FF, HH, Wi, bi, 1, px0, pY, pYd, pdinv);
    run_gcn(px0, pA0, NN, HH, HH, dW, db, 1, pxs0, pY, pYd, pdinv);

    // ================= down path =================
    // i = 1 (4096 -> 2048): tensor-core augment (tf32 exact: entries <= ~1+2)
    {
        int nt = NN / 128;
        augment_mma_k<<<nt * (nt + 1) / 2, 256, AUG_SMEM>>>(pA0, pAaug, NN);
    }
    score_k<<<(NN + 255) / 256, 256>>>(pxs0, pp + 0, pscore, NN);
    sort_topk_k<<<1, 1024>>>(pscore, NN, pp0, 2048);
    gather_h_k<<<(2048 * HH + 255) / 256, 256>>>(pxs0, pp0, pscore, phA, 2048);
    gather_A_k<<<4096, 256>>>(pAaug, NN, pp0, pA1, 2048);
    run_gcn(phA, pA1, 2048, HH, HH, dW + 1024, db + 32, 1, pxs1, pY, pYd, pdinv);

    // i = 2 (2048 -> 1024): tensor-core augment (entries <= max_deg+2 < 2048, tf32 exact)
    {
        int nt = 2048 / 128;
        augment_mma_k<<<nt * (nt + 1) / 2, 256, AUG_SMEM>>>(pA1, pAaug, 2048);
    }
    score_k<<<(2048 + 255) / 256, 256>>>(pxs1, pp + 32, pscore, 2048);
    sort_topk_k<<<1, 1024>>>(pscore, 2048, pp1, 1024);
    gather_h_k<<<(1024 * HH + 255) / 256, 256>>>(pxs1, pp1, pscore, phA, 1024);
    gather_A_k<<<2048, 256>>>(pAaug, 2048, pp1, pA2, 1024);
    run_gcn(phA, pA2, 1024, HH, HH, dW + 2048, db + 64, 1, pxs2, pY, pYd, pdinv);

    // i = 3 (1024 -> 512): fp32 augment (entries may exceed tf32 exact-int range)
    sgemm_k<<<dim3(1024 / 64, 1024 / 64), dim3(16, 16)>>>(pA2, pA2, pAaug, 1024, 1024, 1024);
    score_k<<<(1024 + 255) / 256, 256>>>(pxs2, pp + 64, pscore, 1024);
    sort_topk_k<<<1, 1024>>>(pscore, 1024, pp2, 512);
    gather_h_k<<<(512 * HH + 255) / 256, 256>>>(pxs2, pp2, pscore, phA, 512);
    gather_A_k<<<1024, 256>>>(pAaug, 1024, pp2, pA3, 512);
    run_gcn(phA, pA3, 512, HH, HH, dW + 3072, db + 96, 1, phB, pY, pYd, pdinv);

    // ================= up path =================
    cudaMemcpyAsync(phA, pxs2, (size_t)1024 * HH * sizeof(float), cudaMemcpyDeviceToDevice);
    scatter_add_k<<<(512 * HH + 255) / 256, 256>>>(phA, phB, pp2, 512);
    run_gcn(phA, pA2, 1024, HH, HH, uW, ub, 1, phB, pY, pYd, pdinv);

    cudaMemcpyAsync(phA, pxs1, (size_t)2048 * HH * sizeof(float), cudaMemcpyDeviceToDevice);
    scatter_add_k<<<(1024 * HH + 255) / 256, 256>>>(phA, phB, pp1, 1024);
    run_gcn(phA, pA1, 2048, HH, HH, uW + 1024, ub + 32, 1, phB, pY, pYd, pdinv);

    cudaMemcpyAsync(phA, pxs0, (size_t)NN * HH * sizeof(float), cudaMemcpyDeviceToDevice);
    scatter_add_k<<<(2048 * HH + 255) / 256, 256>>>(phA, phB, pp0, 2048);
    run_gcn(phA, pA0, NN, HH, HH, uW + 2048, ub + 64, 1, phB, pY, pYd, pdinv);

    // ---- final gcn + log_softmax ----
    run_gcn(phB, pA0, NN, HH, CC, Wf, bf, 0, phA, pY, pYd, pdinv);
    logsoftmax_k<<<(NN + 255) / 256, 256>>>(phA, out, NN);
}